// round 2
// baseline (speedup 1.0000x reference)
#include <cuda_runtime.h>
#include <math.h>

#define TT  8192
#define HH  1024
#define EE  8
#define CAP 1280
#define IRR 4096
#define ISS 8192

// Scratch (device globals are the sanctioned scratch mechanism)
__device__ float g_sh[(size_t)TT * ISS];        // shared-expert hidden (gate, then act in-place)  256MB
__device__ float g_rb[(size_t)EE * CAP * IRR];  // routed hidden (gate, then act in-place)          168MB
__device__ int   g_tki[TT * 2];
__device__ float g_tkw[TT * 2];
__device__ int   g_disp[EE * CAP];
__device__ float g_gw[EE * CAP];

// ---------------- Router: RMSNorm + logits + softmax top-2 ----------------
__global__ void router_kernel(const float* __restrict__ x, const float* __restrict__ rw)
{
    int t = blockIdx.x;
    const float* xr = x + (size_t)t * HH;
    float ss = 0.f;
    float dot[EE];
#pragma unroll
    for (int e = 0; e < EE; e++) dot[e] = 0.f;
    for (int i = threadIdx.x; i < HH; i += 256) {
        float v = xr[i];
        ss += v * v;
#pragma unroll
        for (int e = 0; e < EE; e++) dot[e] += v * rw[e * HH + i];
    }
#pragma unroll
    for (int off = 16; off > 0; off >>= 1) {
        ss += __shfl_down_sync(0xffffffffu, ss, off);
#pragma unroll
        for (int e = 0; e < EE; e++) dot[e] += __shfl_down_sync(0xffffffffu, dot[e], off);
    }
    __shared__ float red[8][9];
    int warp = threadIdx.x >> 5, lane = threadIdx.x & 31;
    if (lane == 0) {
        red[warp][0] = ss;
#pragma unroll
        for (int e = 0; e < EE; e++) red[warp][1 + e] = dot[e];
    }
    __syncthreads();
    if (threadIdx.x == 0) {
        float s = 0.f, d[EE];
#pragma unroll
        for (int e = 0; e < EE; e++) d[e] = 0.f;
        for (int w2 = 0; w2 < 8; w2++) {
            s += red[w2][0];
#pragma unroll
            for (int e = 0; e < EE; e++) d[e] += red[w2][1 + e];
        }
        float r = rsqrtf(s / (float)HH + 1.1920929e-7f);
        float lg[EE];
#pragma unroll
        for (int e = 0; e < EE; e++) lg[e] = d[e] * r;
        int i1 = 0;
        for (int e = 1; e < EE; e++) if (lg[e] > lg[i1]) i1 = e;
        int i2 = -1;
        for (int e = 0; e < EE; e++) {
            if (e == i1) continue;
            if (i2 < 0 || lg[e] > lg[i2]) i2 = e;
        }
        float e2 = expf(lg[i2] - lg[i1]);
        float inv = 1.f / (1.f + e2);
        g_tki[t * 2]     = i1;
        g_tki[t * 2 + 1] = i2;
        g_tkw[t * 2]     = inv;
        g_tkw[t * 2 + 1] = e2 * inv;
    }
}

// ------------- Dispatch: per-expert stable capacity fill via prefix scan -------------
__global__ void dispatch_kernel()
{
    int e = blockIdx.x;
    int tid = threadIdx.x;  // 256 threads
    __shared__ int scan[256];
    __shared__ int base_s;
    for (int s = tid; s < CAP; s += 256) {
        g_disp[e * CAP + s] = 0;
        g_gw[e * CAP + s] = 0.f;
    }
    if (tid == 0) base_s = 0;
    __syncthreads();
    for (int c0 = 0; c0 < TT; c0 += 256) {
        int t = c0 + tid;
        int i0 = g_tki[t * 2], i1 = g_tki[t * 2 + 1];
        float wt = (i0 == e) ? g_tkw[t * 2] : ((i1 == e) ? g_tkw[t * 2 + 1] : 0.f);
        int sel = (i0 == e) || (i1 == e);
        scan[tid] = sel;
        __syncthreads();
        for (int off = 1; off < 256; off <<= 1) {
            int v = (tid >= off) ? scan[tid - off] : 0;
            __syncthreads();
            scan[tid] += v;
            __syncthreads();
        }
        int slot = base_s + scan[tid] - 1;
        if (sel && slot < CAP) {
            g_disp[e * CAP + slot] = t;
            g_gw[e * CAP + slot] = wt;
        }
        __syncthreads();
        if (tid == 0) base_s += scan[255];
        __syncthreads();
    }
}

// ------------- Generic register-blocked SGEMM -------------
// C[M,N] = A[M,K] @ B[K,N], row-major. 128x128x16 tiles, 8x8 per-thread.
// GATHER: A row r comes from x[disp[z*CAP+r]] (expert token gather)
// EPI 0: C = acc        (store)
// EPI 1: C = silu(C)*acc (fused gate-act, in-place; C held gate, acc is up)
// EPI 2: atomicAdd(out[disp[...]][col], w * acc)  (weighted scatter)
template <bool GATHER, int EPI>
__global__ void __launch_bounds__(256, 2) sgemm_k(
    const float* __restrict__ A, const float* __restrict__ B, float* __restrict__ C,
    int M, int N, int Kd,
    size_t sA, size_t sB, size_t sC,
    const int* __restrict__ disp, const float* __restrict__ wv,
    float* __restrict__ outp)
{
    __shared__ float As[16][128];
    __shared__ float Bs[16][128];
    int z = blockIdx.z;
    const float* Az = A + (size_t)z * sA;
    const float* Bz = B + (size_t)z * sB;
    float* Cz = C + (size_t)z * sC;
    int bm = blockIdx.y * 128, bn = blockIdx.x * 128;
    int tid = threadIdx.x;
    int tx = tid & 15, ty = tid >> 4;

    float acc[8][8];
#pragma unroll
    for (int i = 0; i < 8; i++)
#pragma unroll
        for (int j = 0; j < 8; j++) acc[i][j] = 0.f;

    // Precompute A row base pointers for the two per-thread loads
    const float* arow[2];
#pragma unroll
    for (int i = 0; i < 2; i++) {
        int id = tid * 2 + i;
        int r = id >> 2;
        int grow = bm + r;
        if (GATHER) {
            int tok = disp[z * CAP + grow];
            arow[i] = A + (size_t)tok * Kd;
        } else {
            arow[i] = Az + (size_t)grow * Kd;
        }
    }

    for (int k0 = 0; k0 < Kd; k0 += 16) {
#pragma unroll
        for (int i = 0; i < 2; i++) {
            int id = tid * 2 + i;
            int r = id >> 2, c4 = (id & 3) * 4;
            float4 v = *(const float4*)(arow[i] + k0 + c4);
            As[c4 + 0][r] = v.x;
            As[c4 + 1][r] = v.y;
            As[c4 + 2][r] = v.z;
            As[c4 + 3][r] = v.w;
        }
#pragma unroll
        for (int i = 0; i < 2; i++) {
            int id = tid * 2 + i;
            int r = id >> 5, c4 = (id & 31) * 4;
            *(float4*)&Bs[r][c4] = *(const float4*)(Bz + (size_t)(k0 + r) * N + bn + c4);
        }
        __syncthreads();
#pragma unroll
        for (int kk = 0; kk < 16; kk++) {
            float a[8], b[8];
#pragma unroll
            for (int i = 0; i < 8; i++) a[i] = As[kk][ty * 8 + i];
#pragma unroll
            for (int j = 0; j < 8; j++) b[j] = Bs[kk][tx * 8 + j];
#pragma unroll
            for (int i = 0; i < 8; i++)
#pragma unroll
                for (int j = 0; j < 8; j++) acc[i][j] = fmaf(a[i], b[j], acc[i][j]);
        }
        __syncthreads();
    }

    int row0 = bm + ty * 8, col0 = bn + tx * 8;
    if (EPI == 0) {
#pragma unroll
        for (int i = 0; i < 8; i++) {
            float* cp = Cz + (size_t)(row0 + i) * N + col0;
            *(float4*)(cp + 0) = make_float4(acc[i][0], acc[i][1], acc[i][2], acc[i][3]);
            *(float4*)(cp + 4) = make_float4(acc[i][4], acc[i][5], acc[i][6], acc[i][7]);
        }
    } else if (EPI == 1) {
#pragma unroll
        for (int i = 0; i < 8; i++) {
            float* cp = Cz + (size_t)(row0 + i) * N + col0;
            float4 g0 = *(const float4*)(cp + 0);
            float4 g1 = *(const float4*)(cp + 4);
            float gv[8] = {g0.x, g0.y, g0.z, g0.w, g1.x, g1.y, g1.z, g1.w};
            float rv[8];
#pragma unroll
            for (int j = 0; j < 8; j++) {
                float g = gv[j];
                float s = g / (1.f + expf(-g));
                rv[j] = s * acc[i][j];
            }
            *(float4*)(cp + 0) = make_float4(rv[0], rv[1], rv[2], rv[3]);
            *(float4*)(cp + 4) = make_float4(rv[4], rv[5], rv[6], rv[7]);
        }
    } else {
#pragma unroll
        for (int i = 0; i < 8; i++) {
            int slot = z * CAP + row0 + i;
            int tok = disp[slot];
            float w = wv[slot];
            float* op = outp + (size_t)tok * HH + col0;
#pragma unroll
            for (int j = 0; j < 8; j++) atomicAdd(op + j, w * acc[i][j]);
        }
    }
}

extern "C" void kernel_launch(void* const* d_in, const int* in_sizes, int n_in,
                              void* d_out, int out_size)
{
    const float* x  = (const float*)d_in[0];
    const float* rw = (const float*)d_in[1];
    const float* rg = (const float*)d_in[2];
    const float* ru = (const float*)d_in[3];
    const float* rd = (const float*)d_in[4];
    const float* sg = (const float*)d_in[5];
    const float* su = (const float*)d_in[6];
    const float* sd = (const float*)d_in[7];
    float* out = (float*)d_out;

    float *p_sh, *p_rb, *p_gw;
    int *p_disp;
    cudaGetSymbolAddress((void**)&p_sh, g_sh);
    cudaGetSymbolAddress((void**)&p_rb, g_rb);
    cudaGetSymbolAddress((void**)&p_gw, g_gw);
    cudaGetSymbolAddress((void**)&p_disp, g_disp);

    // 1. router + dispatch
    router_kernel<<<TT, 256>>>(x, rw);
    dispatch_kernel<<<EE, 256>>>();

    // 2. shared expert: g = x@sg ; act = silu(g)*(x@su) ; out = act@sd
    dim3 gsh(ISS / 128, TT / 128);
    sgemm_k<false, 0><<<gsh, 256>>>(x, sg, p_sh, TT, ISS, HH, 0, 0, 0, nullptr, nullptr, nullptr);
    sgemm_k<false, 1><<<gsh, 256>>>(x, su, p_sh, TT, ISS, HH, 0, 0, 0, nullptr, nullptr, nullptr);
    dim3 gsd(HH / 128, TT / 128);
    sgemm_k<false, 0><<<gsd, 256>>>(p_sh, sd, out, TT, HH, ISS, 0, 0, 0, nullptr, nullptr, nullptr);

    // 3. routed experts (batched over z=expert): gathered A rows from x
    dim3 grt(IRR / 128, CAP / 128, EE);
    sgemm_k<true, 0><<<grt, 256>>>(x, rg, p_rb, CAP, IRR, HH,
                                   0, (size_t)HH * IRR, (size_t)CAP * IRR,
                                   p_disp, nullptr, nullptr);
    sgemm_k<true, 1><<<grt, 256>>>(x, ru, p_rb, CAP, IRR, HH,
                                   0, (size_t)HH * IRR, (size_t)CAP * IRR,
                                   p_disp, nullptr, nullptr);

    // 4. routed down-proj + weighted scatter-add into out (after shared wrote it)
    dim3 grd(HH / 128, CAP / 128, EE);
    sgemm_k<false, 2><<<grd, 256>>>(p_rb, rd, p_rb /*unused*/, CAP, HH, IRR,
                                    (size_t)CAP * IRR, (size_t)IRR * HH, 0,
                                    p_disp, p_gw, out);
}

// round 7
// speedup vs baseline: 2.0570x; 2.0570x over previous
#include <cuda_runtime.h>
#include <cuda_bf16.h>
#include <math.h>
#include <stdint.h>

#define TT  8192
#define HH  1024
#define EE  8
#define CAP 1280
#define IRR 4096
#define ISS 8192

// smem layout (bytes): A hi/lo 128 rows x 80B, B hi/lo 32 rows x 272B
#define A_HI 0
#define A_LO 10240
#define B_HI 20480
#define B_LO 29184
#define SM_TOT 37888

__device__ float g_sh[(size_t)TT * ISS];
__device__ float g_rb[(size_t)EE * CAP * IRR];
__device__ int   g_tki[TT * 2];
__device__ float g_tkw[TT * 2];
__device__ int   g_disp[EE * CAP];
__device__ float g_gw[EE * CAP];

__device__ __forceinline__ uint32_t smem_u32(const void* p) {
    uint32_t a;
    asm("{ .reg .u64 t; cvta.to.shared.u64 t, %1; cvt.u32.u64 %0, t; }" : "=r"(a) : "l"(p));
    return a;
}
__device__ __forceinline__ void ldsm4(uint32_t* r, uint32_t addr) {
    asm volatile("ldmatrix.sync.aligned.m8n8.x4.shared.b16 {%0,%1,%2,%3}, [%4];"
        : "=r"(r[0]), "=r"(r[1]), "=r"(r[2]), "=r"(r[3]) : "r"(addr));
}
__device__ __forceinline__ void ldsm4t(uint32_t* r, uint32_t addr) {
    asm volatile("ldmatrix.sync.aligned.m8n8.x4.trans.shared.b16 {%0,%1,%2,%3}, [%4];"
        : "=r"(r[0]), "=r"(r[1]), "=r"(r[2]), "=r"(r[3]) : "r"(addr));
}
__device__ __forceinline__ void mma16816(float* d, const uint32_t* a, uint32_t b0, uint32_t b1) {
    asm volatile("mma.sync.aligned.m16n8k16.row.col.f32.bf16.bf16.f32 "
        "{%0,%1,%2,%3}, {%4,%5,%6,%7}, {%8,%9}, {%0,%1,%2,%3};"
        : "+f"(d[0]), "+f"(d[1]), "+f"(d[2]), "+f"(d[3])
        : "r"(a[0]), "r"(a[1]), "r"(a[2]), "r"(a[3]), "r"(b0), "r"(b1));
}
__device__ __forceinline__ uint32_t b2u(__nv_bfloat162 v) {
    return *(uint32_t*)&v;
}
// 4 f32 -> 4 bf16 hi (uint2) + 4 bf16 lo (uint2)
__device__ __forceinline__ void cvt8(float4 v, uint2& h, uint2& l) {
    __nv_bfloat162 h0 = __floats2bfloat162_rn(v.x, v.y);
    __nv_bfloat162 h1 = __floats2bfloat162_rn(v.z, v.w);
    float rx = v.x - __bfloat162float(h0.x);
    float ry = v.y - __bfloat162float(h0.y);
    float rz = v.z - __bfloat162float(h1.x);
    float rw = v.w - __bfloat162float(h1.y);
    __nv_bfloat162 l0 = __floats2bfloat162_rn(rx, ry);
    __nv_bfloat162 l1 = __floats2bfloat162_rn(rz, rw);
    h.x = b2u(h0); h.y = b2u(h1);
    l.x = b2u(l0); l.y = b2u(l1);
}

__global__ void router_kernel(const float* __restrict__ x, const float* __restrict__ rw)
{
    int t = blockIdx.x;
    const float* xr = x + (size_t)t * HH;
    float ss = 0.f, dot[EE];
#pragma unroll
    for (int e = 0; e < EE; e++) dot[e] = 0.f;
    for (int i = threadIdx.x; i < HH; i += 256) {
        float v = xr[i];
        ss += v * v;
#pragma unroll
        for (int e = 0; e < EE; e++) dot[e] += v * rw[e * HH + i];
    }
#pragma unroll
    for (int off = 16; off > 0; off >>= 1) {
        ss += __shfl_down_sync(0xffffffffu, ss, off);
#pragma unroll
        for (int e = 0; e < EE; e++) dot[e] += __shfl_down_sync(0xffffffffu, dot[e], off);
    }
    __shared__ float red[8][9];
    int warp = threadIdx.x >> 5, lane = threadIdx.x & 31;
    if (lane == 0) {
        red[warp][0] = ss;
#pragma unroll
        for (int e = 0; e < EE; e++) red[warp][1 + e] = dot[e];
    }
    __syncthreads();
    if (threadIdx.x == 0) {
        float s = 0.f, d[EE];
#pragma unroll
        for (int e = 0; e < EE; e++) d[e] = 0.f;
        for (int w2 = 0; w2 < 8; w2++) {
            s += red[w2][0];
#pragma unroll
            for (int e = 0; e < EE; e++) d[e] += red[w2][1 + e];
        }
        float r = rsqrtf(s / (float)HH + 1.1920929e-7f);
        float lg[EE];
#pragma unroll
        for (int e = 0; e < EE; e++) lg[e] = d[e] * r;
        int i1 = 0;
        for (int e = 1; e < EE; e++) if (lg[e] > lg[i1]) i1 = e;
        int i2 = -1;
        for (int e = 0; e < EE; e++) {
            if (e == i1) continue;
            if (i2 < 0 || lg[e] > lg[i2]) i2 = e;
        }
        float e2 = expf(lg[i2] - lg[i1]);
        float inv = 1.f / (1.f + e2);
        g_tki[t * 2] = i1; g_tki[t * 2 + 1] = i2;
        g_tkw[t * 2] = inv; g_tkw[t * 2 + 1] = e2 * inv;
    }
}

__global__ void dispatch_kernel()
{
    int e = blockIdx.x, tid = threadIdx.x;
    __shared__ int scan[256];
    __shared__ int base_s;
    for (int s = tid; s < CAP; s += 256) { g_disp[e*CAP+s] = 0; g_gw[e*CAP+s] = 0.f; }
    if (tid == 0) base_s = 0;
    __syncthreads();
    for (int c0 = 0; c0 < TT; c0 += 256) {
        int t = c0 + tid;
        int i0 = g_tki[t*2], i1 = g_tki[t*2+1];
        float wt = (i0 == e) ? g_tkw[t*2] : ((i1 == e) ? g_tkw[t*2+1] : 0.f);
        int sel = (i0 == e) || (i1 == e);
        scan[tid] = sel;
        __syncthreads();
        for (int off = 1; off < 256; off <<= 1) {
            int v = (tid >= off) ? scan[tid - off] : 0;
            __syncthreads();
            scan[tid] += v;
            __syncthreads();
        }
        int slot = base_s + scan[tid] - 1;
        if (sel && slot < CAP) { g_disp[e*CAP+slot] = t; g_gw[e*CAP+slot] = wt; }
        __syncthreads();
        if (tid == 0) base_s += scan[255];
        __syncthreads();
    }
}

// C[M,N] = A[M,K] @ B[K,N], bf16 mma.sync with 3-term hi/lo split.
// GATHER: A row comes from x[disp[...]]. EPI 0 store, 1 silu(C)*acc, 2 weighted scatter.
template <bool GATHER, int EPI>
__global__ void __launch_bounds__(256, 1) hgemm_k(
    const float* __restrict__ A, const float* __restrict__ B, float* __restrict__ C,
    int Kd, int N, size_t sA, size_t sB, size_t sC,
    const int* __restrict__ disp, const float* __restrict__ wv,
    float* __restrict__ outp)
{
    __shared__ char smem[SM_TOT];
    uint32_t sb = smem_u32(smem);
    int tid = threadIdx.x, wid = tid >> 5, lane = tid & 31;
    int z = blockIdx.z;
    int bm = blockIdx.y * 128, bn = blockIdx.x * 128;
    int wm = wid & 1, wn = wid >> 1;     // warp tile: 64 (M) x 32 (N)

    // loader mapping
    int arw = tid >> 1, ahalf = tid & 1;         // A: 128 rows, 2 half-rows of 16 f32
    int bkr = tid >> 3, bseg = tid & 7;          // B: 32 k-rows, 8 segs of 16 f32
    const float* aptr;
    if (GATHER) aptr = A + (size_t)disp[z * CAP + bm + arw] * Kd + ahalf * 16;
    else        aptr = A + (size_t)z * sA + (size_t)(bm + arw) * Kd + ahalf * 16;
    const float* bptr = B + (size_t)z * sB + (size_t)bkr * N + bn + bseg * 16;
    uint32_t a_st = sb + A_HI + (uint32_t)arw * 80u + (uint32_t)ahalf * 32u;
    uint32_t b_st = sb + B_HI + (uint32_t)bkr * 272u + (uint32_t)bseg * 32u;

    // ldmatrix lane address bases
    int li = lane & 15, kh = (lane >> 4) << 3;
    uint32_t a_ld = sb + A_HI + (uint32_t)(wm * 64 + li) * 80u + (uint32_t)kh * 2u;
    uint32_t b_ld = sb + B_HI + (uint32_t)li * 272u + (uint32_t)(wn * 32 + kh) * 2u;

    float acc[4][4][4];
#pragma unroll
    for (int i = 0; i < 4; i++)
#pragma unroll
        for (int j = 0; j < 4; j++)
#pragma unroll
            for (int c = 0; c < 4; c++) acc[i][j][c] = 0.f;

    const int NIT = Kd / 32;
    float4 ra[4], rb[4];
#pragma unroll
    for (int i = 0; i < 4; i++) {
        ra[i] = *(const float4*)(aptr + i * 4);
        rb[i] = *(const float4*)(bptr + i * 4);
    }

    for (int it = 0; it < NIT; it++) {
        // store current chunk (converted) to smem
#pragma unroll
        for (int i = 0; i < 4; i++) {
            uint2 h, l;
            cvt8(ra[i], h, l);
            *(uint2*)(smem + (a_st - sb) + i * 8) = h;
            *(uint2*)(smem + (a_st - sb) + A_LO + i * 8) = l;
            cvt8(rb[i], h, l);
            *(uint2*)(smem + (b_st - sb) + i * 8) = h;
            *(uint2*)(smem + (b_st - sb) + (B_LO - B_HI) + i * 8) = l;
        }
        // prefetch next chunk
        if (it + 1 < NIT) {
            int k0 = (it + 1) * 32;
#pragma unroll
            for (int i = 0; i < 4; i++) {
                ra[i] = *(const float4*)(aptr + k0 + i * 4);
                rb[i] = *(const float4*)(bptr + (size_t)k0 * N + i * 4);
            }
        }
        __syncthreads();
        // compute 2 x k16
#pragma unroll
        for (int k0 = 0; k0 < 32; k0 += 16) {
            uint32_t ah[4][4], al[4][4], bh[2][4], bl[2][4];
#pragma unroll
            for (int mt = 0; mt < 4; mt++) {
                uint32_t ad = a_ld + (uint32_t)mt * 1280u + (uint32_t)k0 * 2u;
                ldsm4(ah[mt], ad);
                ldsm4(al[mt], ad + A_LO);
            }
#pragma unroll
            for (int np = 0; np < 2; np++) {
                uint32_t bd = b_ld + (uint32_t)k0 * 272u + (uint32_t)np * 32u;
                ldsm4t(bh[np], bd);
                ldsm4t(bl[np], bd + (B_LO - B_HI));
            }
#pragma unroll
            for (int mt = 0; mt < 4; mt++)
#pragma unroll
                for (int nt = 0; nt < 4; nt++) {
                    int np = nt >> 1, r = (nt & 1) * 2;
                    mma16816(acc[mt][nt], ah[mt], bh[np][r], bh[np][r + 1]);
                    mma16816(acc[mt][nt], ah[mt], bl[np][r], bl[np][r + 1]);
                    mma16816(acc[mt][nt], al[mt], bh[np][r], bh[np][r + 1]);
                }
        }
        __syncthreads();
    }

    // epilogue: lane owns (row g, cols c,c+1) and (row g+8, cols c,c+1) per tile
    int g = lane >> 2, tg = lane & 3;
#pragma unroll
    for (int mt = 0; mt < 4; mt++) {
#pragma unroll
        for (int nt = 0; nt < 4; nt++) {
            int row0 = bm + wm * 64 + mt * 16 + g;
            int col = bn + wn * 32 + nt * 8 + tg * 2;
            float* d = acc[mt][nt];
            if (EPI == 0) {
                float* p0 = C + (size_t)z * sC + (size_t)row0 * N + col;
                float* p1 = p0 + (size_t)8 * N;
                *(float2*)p0 = make_float2(d[0], d[1]);
                *(float2*)p1 = make_float2(d[2], d[3]);
            } else if (EPI == 1) {
                float* p0 = C + (size_t)z * sC + (size_t)row0 * N + col;
                float* p1 = p0 + (size_t)8 * N;
                float2 g0 = *(float2*)p0;
                float2 g1 = *(float2*)p1;
                float2 o0, o1;
                o0.x = g0.x / (1.f + expf(-g0.x)) * d[0];
                o0.y = g0.y / (1.f + expf(-g0.y)) * d[1];
                o1.x = g1.x / (1.f + expf(-g1.x)) * d[2];
                o1.y = g1.y / (1.f + expf(-g1.y)) * d[3];
                *(float2*)p0 = o0;
                *(float2*)p1 = o1;
            } else {
                int s0 = z * CAP + row0, s1 = s0 + 8;
                int t0 = disp[s0], t1 = disp[s1];
                float w0 = wv[s0], w1 = wv[s1];
                float* p0 = outp + (size_t)t0 * HH + col;
                float* p1 = outp + (size_t)t1 * HH + col;
                atomicAdd(p0 + 0, w0 * d[0]);
                atomicAdd(p0 + 1, w0 * d[1]);
                atomicAdd(p1 + 0, w1 * d[2]);
                atomicAdd(p1 + 1, w1 * d[3]);
            }
        }
    }
}

extern "C" void kernel_launch(void* const* d_in, const int* in_sizes, int n_in,
                              void* d_out, int out_size)
{
    const float* x  = (const float*)d_in[0];
    const float* rw = (const float*)d_in[1];
    const float* rg = (const float*)d_in[2];
    const float* ru = (const float*)d_in[3];
    const float* rd = (const float*)d_in[4];
    const float* sg = (const float*)d_in[5];
    const float* su = (const float*)d_in[6];
    const float* sd = (const float*)d_in[7];
    float* out = (float*)d_out;

    float *p_sh, *p_rb, *p_gw;
    int *p_disp;
    cudaGetSymbolAddress((void**)&p_sh, g_sh);
    cudaGetSymbolAddress((void**)&p_rb, g_rb);
    cudaGetSymbolAddress((void**)&p_gw, g_gw);
    cudaGetSymbolAddress((void**)&p_disp, g_disp);

    router_kernel<<<TT, 256>>>(x, rw);
    dispatch_kernel<<<EE, 256>>>();

    // shared expert
    dim3 gsh(ISS / 128, TT / 128);
    hgemm_k<false, 0><<<gsh, 256>>>(x, sg, p_sh, HH, ISS, 0, 0, 0, (const int*)0, (const float*)0, (float*)0);
    hgemm_k<false, 1><<<gsh, 256>>>(x, su, p_sh, HH, ISS, 0, 0, 0, (const int*)0, (const float*)0, (float*)0);
    dim3 gsd(HH / 128, TT / 128);
    hgemm_k<false, 0><<<gsd, 256>>>(p_sh, sd, out, ISS, HH, 0, 0, 0, (const int*)0, (const float*)0, (float*)0);

    // routed experts
    dim3 grt(IRR / 128, CAP / 128, EE);
    hgemm_k<true, 0><<<grt, 256>>>(x, rg, p_rb, HH, IRR,
                                   0, (size_t)HH * IRR, (size_t)CAP * IRR,
                                   p_disp, (const float*)0, (float*)0);
    hgemm_k<true, 1><<<grt, 256>>>(x, ru, p_rb, HH, IRR,
                                   0, (size_t)HH * IRR, (size_t)CAP * IRR,
                                   p_disp, (const float*)0, (float*)0);

    dim3 grd(HH / 128, CAP / 128, EE);
    hgemm_k<false, 2><<<grd, 256>>>(p_rb, rd, (float*)0, IRR, HH,
                                    (size_t)CAP * IRR, (size_t)IRR * HH, 0,
                                    p_disp, p_gw, out);
}